// round 1
// baseline (speedup 1.0000x reference)
#include <cuda_runtime.h>
#include <math.h>

// Problem constants (fixed by the dataset)
#define B_    256
#define S_    196
#define RNN_  1024
#define ATTH_ 512

// Scratch (allocation-free: __device__ globals)
__device__ float g_att_h[B_ * ATTH_];   // 512 KB
__device__ float g_wgt[B_ * S_];        // 200 KB

// ---------------------------------------------------------------------------
// K1: att_h[b,a] = sum_k h[b,k] * W[a,k] + bias[a]
// Tiled GEMM: BM=64 (b), BN=64 (a), BK=32. 256 threads, 4x4 microtile.
// grid = (ATTH/64, B/64) = (8, 4)
// ---------------------------------------------------------------------------
__global__ __launch_bounds__(256) void k1_h2att(
    const float* __restrict__ h, const float* __restrict__ w,
    const float* __restrict__ bias, float* __restrict__ att_h)
{
    __shared__ float sh[64][33];
    __shared__ float sw[64][33];
    const int tx = threadIdx.x & 15;
    const int ty = threadIdx.x >> 4;
    const int a0 = blockIdx.x * 64;
    const int b0 = blockIdx.y * 64;

    float acc[4][4] = {};

    for (int k0 = 0; k0 < RNN_; k0 += 32) {
        #pragma unroll
        for (int i = 0; i < 8; i++) {
            int e = threadIdx.x + i * 256;
            int r = e >> 5, c = e & 31;
            sh[r][c] = h[(size_t)(b0 + r) * RNN_ + k0 + c];
            sw[r][c] = w[(size_t)(a0 + r) * RNN_ + k0 + c];
        }
        __syncthreads();
        #pragma unroll
        for (int kk = 0; kk < 32; kk++) {
            float hv[4], wv[4];
            #pragma unroll
            for (int i = 0; i < 4; i++) hv[i] = sh[ty * 4 + i][kk];
            #pragma unroll
            for (int j = 0; j < 4; j++) wv[j] = sw[tx * 4 + j][kk];
            #pragma unroll
            for (int i = 0; i < 4; i++)
                #pragma unroll
                for (int j = 0; j < 4; j++)
                    acc[i][j] += hv[i] * wv[j];
        }
        __syncthreads();
    }

    #pragma unroll
    for (int i = 0; i < 4; i++) {
        int bb = b0 + ty * 4 + i;
        #pragma unroll
        for (int j = 0; j < 4; j++) {
            int aa = a0 + tx * 4 + j;
            att_h[(size_t)bb * ATTH_ + aa] = acc[i][j] + bias[aa];
        }
    }
}

// ---------------------------------------------------------------------------
// K2: scores[b,s] = sum_a tanh(p[b,s,a] + att_h[b,a]) * w_alpha[a]
//     weight[b,:] = softmax(scores[b,:])   (b_alpha dropped: softmax-invariant)
// grid = B blocks, 256 threads (8 warps). Warp per s-row, lanes stride a.
// ---------------------------------------------------------------------------
__global__ __launch_bounds__(256) void k2_scores_softmax(
    const float* __restrict__ p, const float* __restrict__ att_h,
    const float* __restrict__ w_alpha, float* __restrict__ wgt)
{
    const int b = blockIdx.x;
    const int t = threadIdx.x;
    __shared__ float ah[ATTH_];
    __shared__ float wa[ATTH_];
    __shared__ float sc[256];
    __shared__ float red[256];

    for (int i = t; i < ATTH_; i += 256) {
        ah[i] = att_h[(size_t)b * ATTH_ + i];
        wa[i] = w_alpha[i];
    }
    __syncthreads();

    const int warp = t >> 5, lane = t & 31;
    const float* pb = p + (size_t)b * S_ * ATTH_;

    for (int s = warp; s < S_; s += 8) {
        const float* ps = pb + (size_t)s * ATTH_;
        float acc = 0.f;
        #pragma unroll
        for (int i = 0; i < ATTH_ / 32; i++) {
            int a = lane + i * 32;
            acc += tanhf(ps[a] + ah[a]) * wa[a];
        }
        #pragma unroll
        for (int o = 16; o; o >>= 1)
            acc += __shfl_xor_sync(0xffffffffu, acc, o);
        if (lane == 0) sc[s] = acc;
    }
    __syncthreads();

    // softmax over S_=196 scores
    float v = (t < S_) ? sc[t] : -INFINITY;
    red[t] = v;
    __syncthreads();
    for (int o = 128; o; o >>= 1) {
        if (t < o) red[t] = fmaxf(red[t], red[t + o]);
        __syncthreads();
    }
    const float m = red[0];
    __syncthreads();
    float e = (t < S_) ? __expf(v - m) : 0.f;
    red[t] = e;
    __syncthreads();
    for (int o = 128; o; o >>= 1) {
        if (t < o) red[t] += red[t + o];
        __syncthreads();
    }
    const float inv = 1.f / red[0];
    if (t < S_) wgt[(size_t)b * S_ + t] = e * inv;
}

// ---------------------------------------------------------------------------
// K3: out[b,d] = sum_s weight[b,s] * att_feats[b,s,d]
// grid = (2, B), 128 threads; each thread owns one float4 column (512 d/block)
// ---------------------------------------------------------------------------
__global__ __launch_bounds__(128) void k3_weighted_sum(
    const float* __restrict__ att, const float* __restrict__ wgt,
    float* __restrict__ out)
{
    const int b = blockIdx.y;
    const int dbase = blockIdx.x * 512 + threadIdx.x * 4;
    __shared__ float w_s[S_];
    for (int i = threadIdx.x; i < S_; i += 128)
        w_s[i] = wgt[(size_t)b * S_ + i];
    __syncthreads();

    const float4* ap = (const float4*)(att + (size_t)b * S_ * RNN_ + dbase);
    float4 acc = make_float4(0.f, 0.f, 0.f, 0.f);
    #pragma unroll 4
    for (int s = 0; s < S_; s++) {
        const float w = w_s[s];
        const float4 v = ap[(size_t)s * (RNN_ / 4)];
        acc.x += w * v.x;
        acc.y += w * v.y;
        acc.z += w * v.z;
        acc.w += w * v.w;
    }
    *(float4*)(out + (size_t)b * RNN_ + dbase) = acc;
}

// ---------------------------------------------------------------------------
extern "C" void kernel_launch(void* const* d_in, const int* in_sizes, int n_in,
                              void* d_out, int out_size)
{
    const float* h        = (const float*)d_in[0];  // [B, RNN]
    const float* att      = (const float*)d_in[1];  // [B, S, RNN]
    const float* p        = (const float*)d_in[2];  // [B, S, ATTH]
    const float* w_h2att  = (const float*)d_in[3];  // [ATTH, RNN]
    const float* b_h2att  = (const float*)d_in[4];  // [ATTH]
    const float* w_alpha  = (const float*)d_in[5];  // [1, ATTH]
    // d_in[6] = b_alpha: softmax-invariant, unused
    float* out = (float*)d_out;                     // [B, RNN]

    float* att_h_ptr = nullptr;
    float* wgt_ptr   = nullptr;
    cudaGetSymbolAddress((void**)&att_h_ptr, g_att_h);
    cudaGetSymbolAddress((void**)&wgt_ptr, g_wgt);

    k1_h2att<<<dim3(ATTH_ / 64, B_ / 64), 256>>>(h, w_h2att, b_h2att, att_h_ptr);
    k2_scores_softmax<<<B_, 256>>>(p, att_h_ptr, w_alpha, wgt_ptr);
    k3_weighted_sum<<<dim3(2, B_), 128>>>(att, wgt_ptr, out);
}

// round 2
// speedup vs baseline: 1.2159x; 1.2159x over previous
#include <cuda_runtime.h>
#include <math.h>

// Problem constants (fixed by the dataset)
#define B_    256
#define S_    196
#define RNN_  1024
#define ATTH_ 512

// Scratch (allocation-free: __device__ globals)
__device__ float g_att_h[B_ * ATTH_];    // 512 KB
__device__ float g_scores[B_ * S_];      // 200 KB
__device__ float g_wgt[B_ * S_];         // 200 KB

// ---------------------------------------------------------------------------
// fast tanh: tanh(x) = 1 - 2/(exp(2x)+1). 2 MUFU + ~4 FMA, abs err ~1e-7.
// Saturates correctly at +-1 for large |x| (exp -> inf/0).
// ---------------------------------------------------------------------------
__device__ __forceinline__ float fast_tanh(float x)
{
    float e = __expf(2.0f * x);
    return 1.0f - __fdividef(2.0f, e + 1.0f);
}

// ---------------------------------------------------------------------------
// K1: att_h[b,a] = sum_k h[b,k] * W[a,k] + bias[a]
// 32x32 tiles, BK=32, 256 threads, 2x2 microtile, k-major smem (float2 reads).
// grid = (ATTH/32, B/32) = (16, 8) = 128 blocks -> one wave, FMA-pipe bound.
// ---------------------------------------------------------------------------
__global__ __launch_bounds__(256) void k1_h2att(
    const float* __restrict__ h, const float* __restrict__ w,
    const float* __restrict__ bias, float* __restrict__ att_h)
{
    __shared__ float sh[32][34];   // [k][b]  (pad 34 keeps float2 aligned)
    __shared__ float sw[32][34];   // [k][a]

    const int t  = threadIdx.x;
    const int a0 = blockIdx.x * 32;
    const int b0 = blockIdx.y * 32;
    const int tx = t & 15;         // a-dim (x2)
    const int ty = t >> 4;         // b-dim (x2)

    // global-load mapping: 256 threads, 1 float4 each per tile
    const int lr = t >> 3;         // row within tile (0..31)
    const int lc = (t & 7) * 4;    // k-col within tile (0,4,..,28)

    float acc00 = 0.f, acc01 = 0.f, acc10 = 0.f, acc11 = 0.f;

    for (int k0 = 0; k0 < RNN_; k0 += 32) {
        float4 hv = *(const float4*)&h[(size_t)(b0 + lr) * RNN_ + k0 + lc];
        float4 wv = *(const float4*)&w[(size_t)(a0 + lr) * RNN_ + k0 + lc];
        sh[lc + 0][lr] = hv.x; sh[lc + 1][lr] = hv.y;
        sh[lc + 2][lr] = hv.z; sh[lc + 3][lr] = hv.w;
        sw[lc + 0][lr] = wv.x; sw[lc + 1][lr] = wv.y;
        sw[lc + 2][lr] = wv.z; sw[lc + 3][lr] = wv.w;
        __syncthreads();

        #pragma unroll
        for (int kk = 0; kk < 32; kk++) {
            float2 hb = *(const float2*)&sh[kk][ty * 2];
            float2 wb = *(const float2*)&sw[kk][tx * 2];
            acc00 += hb.x * wb.x;
            acc01 += hb.x * wb.y;
            acc10 += hb.y * wb.x;
            acc11 += hb.y * wb.y;
        }
        __syncthreads();
    }

    const int bb = b0 + ty * 2;
    const int aa = a0 + tx * 2;
    const float bz0 = bias[aa], bz1 = bias[aa + 1];
    att_h[(size_t)bb * ATTH_ + aa]           = acc00 + bz0;
    att_h[(size_t)bb * ATTH_ + aa + 1]       = acc01 + bz1;
    att_h[(size_t)(bb + 1) * ATTH_ + aa]     = acc10 + bz0;
    att_h[(size_t)(bb + 1) * ATTH_ + aa + 1] = acc11 + bz1;
}

// ---------------------------------------------------------------------------
// K2a: scores[b,s] = sum_a tanh(p[b,s,a] + att_h[b,a]) * w_alpha[a]
// grid = (B, 4): block handles 49 s-rows of one batch. 8 warps, warp per row,
// lanes stride a in float4. 1024 blocks -> good wave balance on 148 SMs.
// ---------------------------------------------------------------------------
__global__ __launch_bounds__(256) void k2a_scores(
    const float* __restrict__ p, const float* __restrict__ att_h,
    const float* __restrict__ w_alpha, float* __restrict__ scores)
{
    const int b     = blockIdx.x;
    const int chunk = blockIdx.y;
    const int t     = threadIdx.x;

    __shared__ float4 ah4[ATTH_ / 4];
    __shared__ float4 wa4[ATTH_ / 4];
    for (int i = t; i < ATTH_ / 4; i += 256) {
        ah4[i] = ((const float4*)(att_h + (size_t)b * ATTH_))[i];
        wa4[i] = ((const float4*)w_alpha)[i];
    }
    __syncthreads();

    const int warp = t >> 5, lane = t & 31;
    const int s_lo = chunk * 49;
    const int s_hi = s_lo + 49;   // 196 = 4*49 exactly

    for (int s = s_lo + warp; s < s_hi; s += 8) {
        const float4* ps = (const float4*)(p + ((size_t)b * S_ + s) * ATTH_);
        float acc = 0.f;
        #pragma unroll
        for (int i = 0; i < 4; i++) {
            const int idx = lane + i * 32;
            float4 v = ps[idx];
            float4 a = ah4[idx];
            float4 wv = wa4[idx];
            acc += fast_tanh(v.x + a.x) * wv.x;
            acc += fast_tanh(v.y + a.y) * wv.y;
            acc += fast_tanh(v.z + a.z) * wv.z;
            acc += fast_tanh(v.w + a.w) * wv.w;
        }
        #pragma unroll
        for (int o = 16; o; o >>= 1)
            acc += __shfl_xor_sync(0xffffffffu, acc, o);
        if (lane == 0) scores[(size_t)b * S_ + s] = acc;
    }
}

// ---------------------------------------------------------------------------
// K2b: weight[b,:] = softmax(scores[b,:])  (b_alpha is softmax-invariant)
// grid = B, 256 threads.
// ---------------------------------------------------------------------------
__global__ __launch_bounds__(256) void k2b_softmax(
    const float* __restrict__ scores, float* __restrict__ wgt)
{
    const int b = blockIdx.x;
    const int t = threadIdx.x;
    __shared__ float red[256];

    float v = (t < S_) ? scores[(size_t)b * S_ + t] : -INFINITY;
    red[t] = v;
    __syncthreads();
    #pragma unroll
    for (int o = 128; o; o >>= 1) {
        if (t < o) red[t] = fmaxf(red[t], red[t + o]);
        __syncthreads();
    }
    const float m = red[0];
    __syncthreads();
    float e = (t < S_) ? __expf(v - m) : 0.f;
    red[t] = e;
    __syncthreads();
    #pragma unroll
    for (int o = 128; o; o >>= 1) {
        if (t < o) red[t] += red[t + o];
        __syncthreads();
    }
    const float inv = 1.f / red[0];
    if (t < S_) wgt[(size_t)b * S_ + t] = e * inv;
}

// ---------------------------------------------------------------------------
// K3: out[b,d] = sum_s weight[b,s] * att_feats[b,s,d]
// grid = (2, B), 128 threads; each thread owns one float4 column.
// 205 MB streamed once, fully coalesced (2KB per block per s-step).
// ---------------------------------------------------------------------------
__global__ __launch_bounds__(128) void k3_weighted_sum(
    const float* __restrict__ att, const float* __restrict__ wgt,
    float* __restrict__ out)
{
    const int b = blockIdx.y;
    const int dbase = blockIdx.x * 512 + threadIdx.x * 4;
    __shared__ float w_s[S_];
    for (int i = threadIdx.x; i < S_; i += 128)
        w_s[i] = wgt[(size_t)b * S_ + i];
    __syncthreads();

    const float4* ap = (const float4*)(att + (size_t)b * S_ * RNN_ + dbase);
    float4 acc = make_float4(0.f, 0.f, 0.f, 0.f);
    #pragma unroll 7
    for (int s = 0; s < S_; s++) {
        const float w = w_s[s];
        const float4 v = ap[(size_t)s * (RNN_ / 4)];
        acc.x += w * v.x;
        acc.y += w * v.y;
        acc.z += w * v.z;
        acc.w += w * v.w;
    }
    *(float4*)(out + (size_t)b * RNN_ + dbase) = acc;
}

// ---------------------------------------------------------------------------
extern "C" void kernel_launch(void* const* d_in, const int* in_sizes, int n_in,
                              void* d_out, int out_size)
{
    const float* h        = (const float*)d_in[0];  // [B, RNN]
    const float* att      = (const float*)d_in[1];  // [B, S, RNN]
    const float* p        = (const float*)d_in[2];  // [B, S, ATTH]
    const float* w_h2att  = (const float*)d_in[3];  // [ATTH, RNN]
    const float* b_h2att  = (const float*)d_in[4];  // [ATTH]
    const float* w_alpha  = (const float*)d_in[5];  // [1, ATTH]
    // d_in[6] = b_alpha: softmax-invariant, unused
    float* out = (float*)d_out;                     // [B, RNN]

    float *att_h_ptr = nullptr, *sc_ptr = nullptr, *wgt_ptr = nullptr;
    cudaGetSymbolAddress((void**)&att_h_ptr, g_att_h);
    cudaGetSymbolAddress((void**)&sc_ptr,    g_scores);
    cudaGetSymbolAddress((void**)&wgt_ptr,   g_wgt);

    k1_h2att<<<dim3(ATTH_ / 32, B_ / 32), 256>>>(h, w_h2att, b_h2att, att_h_ptr);
    k2a_scores<<<dim3(B_, 4), 256>>>(p, att_h_ptr, w_alpha, sc_ptr);
    k2b_softmax<<<B_, 256>>>(sc_ptr, wgt_ptr);
    k3_weighted_sum<<<dim3(2, B_), 128>>>(att, wgt_ptr, out);
}

// round 3
// speedup vs baseline: 1.2786x; 1.0515x over previous
#include <cuda_runtime.h>
#include <math.h>

// Problem constants (fixed by the dataset)
#define B_    256
#define S_    196
#define RNN_  1024
#define ATTH_ 512
#define NSPLIT 4
#define SCHUNK 49   // 196 / 4

// Scratch (allocation-free: __device__ globals)
__device__ float g_att_h[B_ * ATTH_];            // 512 KB
__device__ float g_scores[B_ * S_];              // 200 KB
__device__ float g_wgt[B_ * S_];                 // 200 KB
__device__ float g_part[NSPLIT * B_ * RNN_];     // 4 MB partial sums for k3

// ---------------------------------------------------------------------------
// fast tanh: tanh(x) = 1 - 2/(exp(2x)+1). 2 MUFU + ~4 FMA, abs err ~1e-7.
// ---------------------------------------------------------------------------
__device__ __forceinline__ float fast_tanh(float x)
{
    float e = __expf(2.0f * x);
    return 1.0f - __fdividef(2.0f, e + 1.0f);
}

// ---------------------------------------------------------------------------
// K1: att_h[b,a] = sum_k h[b,k] * W[a,k] + bias[a]
// 32x32 tiles, BK=32, 256 threads, 2x2 microtile, k-major smem.
// grid = (16, 8) = 128 blocks.
// ---------------------------------------------------------------------------
__global__ __launch_bounds__(256) void k1_h2att(
    const float* __restrict__ h, const float* __restrict__ w,
    const float* __restrict__ bias, float* __restrict__ att_h)
{
    __shared__ float sh[32][34];
    __shared__ float sw[32][34];

    const int t  = threadIdx.x;
    const int a0 = blockIdx.x * 32;
    const int b0 = blockIdx.y * 32;
    const int tx = t & 15;
    const int ty = t >> 4;
    const int lr = t >> 3;
    const int lc = (t & 7) * 4;

    float acc00 = 0.f, acc01 = 0.f, acc10 = 0.f, acc11 = 0.f;

    for (int k0 = 0; k0 < RNN_; k0 += 32) {
        float4 hv = *(const float4*)&h[(size_t)(b0 + lr) * RNN_ + k0 + lc];
        float4 wv = *(const float4*)&w[(size_t)(a0 + lr) * RNN_ + k0 + lc];
        sh[lc + 0][lr] = hv.x; sh[lc + 1][lr] = hv.y;
        sh[lc + 2][lr] = hv.z; sh[lc + 3][lr] = hv.w;
        sw[lc + 0][lr] = wv.x; sw[lc + 1][lr] = wv.y;
        sw[lc + 2][lr] = wv.z; sw[lc + 3][lr] = wv.w;
        __syncthreads();

        #pragma unroll
        for (int kk = 0; kk < 32; kk++) {
            float2 hb = *(const float2*)&sh[kk][ty * 2];
            float2 wb = *(const float2*)&sw[kk][tx * 2];
            acc00 += hb.x * wb.x;
            acc01 += hb.x * wb.y;
            acc10 += hb.y * wb.x;
            acc11 += hb.y * wb.y;
        }
        __syncthreads();
    }

    const int bb = b0 + ty * 2;
    const int aa = a0 + tx * 2;
    const float bz0 = bias[aa], bz1 = bias[aa + 1];
    att_h[(size_t)bb * ATTH_ + aa]           = acc00 + bz0;
    att_h[(size_t)bb * ATTH_ + aa + 1]       = acc01 + bz1;
    att_h[(size_t)(bb + 1) * ATTH_ + aa]     = acc10 + bz0;
    att_h[(size_t)(bb + 1) * ATTH_ + aa + 1] = acc11 + bz1;
}

// ---------------------------------------------------------------------------
// K2a: scores[b,s] = sum_a tanh(p[b,s,a] + att_h[b,a]) * w_alpha[a]
// grid = (B, 4): block handles 49 s-rows of one batch; warp per row.
// ---------------------------------------------------------------------------
__global__ __launch_bounds__(256) void k2a_scores(
    const float* __restrict__ p, const float* __restrict__ att_h,
    const float* __restrict__ w_alpha, float* __restrict__ scores)
{
    const int b     = blockIdx.x;
    const int chunk = blockIdx.y;
    const int t     = threadIdx.x;

    __shared__ float4 ah4[ATTH_ / 4];
    __shared__ float4 wa4[ATTH_ / 4];
    for (int i = t; i < ATTH_ / 4; i += 256) {
        ah4[i] = ((const float4*)(att_h + (size_t)b * ATTH_))[i];
        wa4[i] = ((const float4*)w_alpha)[i];
    }
    __syncthreads();

    const int warp = t >> 5, lane = t & 31;
    const int s_lo = chunk * SCHUNK;
    const int s_hi = s_lo + SCHUNK;

    for (int s = s_lo + warp; s < s_hi; s += 8) {
        const float4* ps = (const float4*)(p + ((size_t)b * S_ + s) * ATTH_);
        float acc = 0.f;
        #pragma unroll
        for (int i = 0; i < 4; i++) {
            const int idx = lane + i * 32;
            float4 v = ps[idx];
            float4 a = ah4[idx];
            float4 wv = wa4[idx];
            acc += fast_tanh(v.x + a.x) * wv.x;
            acc += fast_tanh(v.y + a.y) * wv.y;
            acc += fast_tanh(v.z + a.z) * wv.z;
            acc += fast_tanh(v.w + a.w) * wv.w;
        }
        #pragma unroll
        for (int o = 16; o; o >>= 1)
            acc += __shfl_xor_sync(0xffffffffu, acc, o);
        if (lane == 0) scores[(size_t)b * S_ + s] = acc;
    }
}

// ---------------------------------------------------------------------------
// K2b: weight[b,:] = softmax(scores[b,:])
// ---------------------------------------------------------------------------
__global__ __launch_bounds__(256) void k2b_softmax(
    const float* __restrict__ scores, float* __restrict__ wgt)
{
    const int b = blockIdx.x;
    const int t = threadIdx.x;
    __shared__ float red[256];

    float v = (t < S_) ? scores[(size_t)b * S_ + t] : -INFINITY;
    red[t] = v;
    __syncthreads();
    #pragma unroll
    for (int o = 128; o; o >>= 1) {
        if (t < o) red[t] = fmaxf(red[t], red[t + o]);
        __syncthreads();
    }
    const float m = red[0];
    __syncthreads();
    float e = (t < S_) ? __expf(v - m) : 0.f;
    red[t] = e;
    __syncthreads();
    #pragma unroll
    for (int o = 128; o; o >>= 1) {
        if (t < o) red[t] += red[t + o];
        __syncthreads();
    }
    const float inv = 1.f / red[0];
    if (t < S_) wgt[(size_t)b * S_ + t] = e * inv;
}

// ---------------------------------------------------------------------------
// K3a: partial weighted sums, s split 4 ways for occupancy/MLP.
// part[split][b][d] = sum_{s in chunk} w[b,s] * att[b,s,d]
// grid = (2, B, 4) = 2048 blocks, 128 threads; thread owns one float4 col.
// ---------------------------------------------------------------------------
__global__ __launch_bounds__(128) void k3a_partial(
    const float* __restrict__ att, const float* __restrict__ wgt,
    float* __restrict__ part)
{
    const int b     = blockIdx.y;
    const int split = blockIdx.z;
    const int dbase = blockIdx.x * 512 + threadIdx.x * 4;
    const int s_lo  = split * SCHUNK;

    __shared__ float w_s[SCHUNK];
    if (threadIdx.x < SCHUNK)
        w_s[threadIdx.x] = wgt[(size_t)b * S_ + s_lo + threadIdx.x];
    __syncthreads();

    const float4* ap = (const float4*)(att + ((size_t)b * S_ + s_lo) * RNN_ + dbase);
    float4 acc = make_float4(0.f, 0.f, 0.f, 0.f);
    #pragma unroll 7
    for (int s = 0; s < SCHUNK; s++) {
        const float w = w_s[s];
        const float4 v = ap[(size_t)s * (RNN_ / 4)];
        acc.x += w * v.x;
        acc.y += w * v.y;
        acc.z += w * v.z;
        acc.w += w * v.w;
    }
    *(float4*)(part + ((size_t)split * B_ + b) * RNN_ + dbase) = acc;
}

// ---------------------------------------------------------------------------
// K3b: out[b,d] = sum_split part[split][b][d]   (deterministic reduce)
// grid = 256 blocks x 256 threads; thread owns one float4 of out.
// ---------------------------------------------------------------------------
__global__ __launch_bounds__(256) void k3b_reduce(
    const float* __restrict__ part, float* __restrict__ out)
{
    const int idx = blockIdx.x * 256 + threadIdx.x;   // 0 .. B*RNN/4-1
    const float4* p4 = (const float4*)part;
    const int stride = B_ * RNN_ / 4;                 // 65536

    float4 a = p4[idx];
    float4 b = p4[idx + stride];
    float4 c = p4[idx + 2 * stride];
    float4 d = p4[idx + 3 * stride];
    float4 r;
    r.x = (a.x + b.x) + (c.x + d.x);
    r.y = (a.y + b.y) + (c.y + d.y);
    r.z = (a.z + b.z) + (c.z + d.z);
    r.w = (a.w + b.w) + (c.w + d.w);
    ((float4*)out)[idx] = r;
}

// ---------------------------------------------------------------------------
extern "C" void kernel_launch(void* const* d_in, const int* in_sizes, int n_in,
                              void* d_out, int out_size)
{
    const float* h        = (const float*)d_in[0];  // [B, RNN]
    const float* att      = (const float*)d_in[1];  // [B, S, RNN]
    const float* p        = (const float*)d_in[2];  // [B, S, ATTH]
    const float* w_h2att  = (const float*)d_in[3];  // [ATTH, RNN]
    const float* b_h2att  = (const float*)d_in[4];  // [ATTH]
    const float* w_alpha  = (const float*)d_in[5];  // [1, ATTH]
    // d_in[6] = b_alpha: softmax-invariant, unused
    float* out = (float*)d_out;                     // [B, RNN]

    float *att_h_ptr = nullptr, *sc_ptr = nullptr, *wgt_ptr = nullptr, *part_ptr = nullptr;
    cudaGetSymbolAddress((void**)&att_h_ptr, g_att_h);
    cudaGetSymbolAddress((void**)&sc_ptr,    g_scores);
    cudaGetSymbolAddress((void**)&wgt_ptr,   g_wgt);
    cudaGetSymbolAddress((void**)&part_ptr,  g_part);

    k1_h2att<<<dim3(ATTH_ / 32, B_ / 32), 256>>>(h, w_h2att, b_h2att, att_h_ptr);
    k2a_scores<<<dim3(B_, 4), 256>>>(p, att_h_ptr, w_alpha, sc_ptr);
    k2b_softmax<<<B_, 256>>>(sc_ptr, wgt_ptr);
    k3a_partial<<<dim3(2, B_, NSPLIT), 128>>>(att, wgt_ptr, part_ptr);
    k3b_reduce<<<B_ * RNN_ / 4 / 256, 256>>>(part_ptr, out);
}

// round 4
// speedup vs baseline: 1.4123x; 1.1045x over previous
#include <cuda_runtime.h>
#include <math.h>

// Problem constants (fixed by the dataset)
#define B_    256
#define S_    196
#define RNN_  1024
#define ATTH_ 512
#define NSPLIT 7
#define SCHUNK 28   // 196 / 7

// Scratch (allocation-free: __device__ globals)
__device__ float g_att_h[B_ * ATTH_];            // 512 KB
__device__ float g_scores[B_ * S_];              // 200 KB
__device__ float g_part[NSPLIT * B_ * RNN_];     // 7 MB partial sums for k3

// ---------------------------------------------------------------------------
// fast tanh: tanh(x) = 1 - 2/(exp(2x)+1). 2 MUFU + ~4 FMA, abs err ~1e-7.
// ---------------------------------------------------------------------------
__device__ __forceinline__ float fast_tanh(float x)
{
    float e = __expf(2.0f * x);
    return 1.0f - __fdividef(2.0f, e + 1.0f);
}

// ---------------------------------------------------------------------------
// K1: att_h[b,a] = sum_k h[b,k] * W[a,k] + bias[a]
// 32x32 tiles, BK=32, 256 threads, 2x2 microtile, k-major smem.
// grid = (16, 8) = 128 blocks.
// ---------------------------------------------------------------------------
__global__ __launch_bounds__(256) void k1_h2att(
    const float* __restrict__ h, const float* __restrict__ w,
    const float* __restrict__ bias, float* __restrict__ att_h)
{
    __shared__ float sh[32][34];
    __shared__ float sw[32][34];

    const int t  = threadIdx.x;
    const int a0 = blockIdx.x * 32;
    const int b0 = blockIdx.y * 32;
    const int tx = t & 15;
    const int ty = t >> 4;
    const int lr = t >> 3;
    const int lc = (t & 7) * 4;

    float acc00 = 0.f, acc01 = 0.f, acc10 = 0.f, acc11 = 0.f;

    for (int k0 = 0; k0 < RNN_; k0 += 32) {
        float4 hv = *(const float4*)&h[(size_t)(b0 + lr) * RNN_ + k0 + lc];
        float4 wv = *(const float4*)&w[(size_t)(a0 + lr) * RNN_ + k0 + lc];
        sh[lc + 0][lr] = hv.x; sh[lc + 1][lr] = hv.y;
        sh[lc + 2][lr] = hv.z; sh[lc + 3][lr] = hv.w;
        sw[lc + 0][lr] = wv.x; sw[lc + 1][lr] = wv.y;
        sw[lc + 2][lr] = wv.z; sw[lc + 3][lr] = wv.w;
        __syncthreads();

        #pragma unroll
        for (int kk = 0; kk < 32; kk++) {
            float2 hb = *(const float2*)&sh[kk][ty * 2];
            float2 wb = *(const float2*)&sw[kk][tx * 2];
            acc00 += hb.x * wb.x;
            acc01 += hb.x * wb.y;
            acc10 += hb.y * wb.x;
            acc11 += hb.y * wb.y;
        }
        __syncthreads();
    }

    const int bb = b0 + ty * 2;
    const int aa = a0 + tx * 2;
    const float bz0 = bias[aa], bz1 = bias[aa + 1];
    att_h[(size_t)bb * ATTH_ + aa]           = acc00 + bz0;
    att_h[(size_t)bb * ATTH_ + aa + 1]       = acc01 + bz1;
    att_h[(size_t)(bb + 1) * ATTH_ + aa]     = acc10 + bz0;
    att_h[(size_t)(bb + 1) * ATTH_ + aa + 1] = acc11 + bz1;
}

// ---------------------------------------------------------------------------
// K2a: scores[b,s] = sum_a tanh(p[b,s,a] + att_h[b,a]) * w_alpha[a]
// grid = (B, 4): block handles 49 s-rows of one batch; warp per row.
// Dual accumulators + streaming loads on p.
// ---------------------------------------------------------------------------
__global__ __launch_bounds__(256) void k2a_scores(
    const float* __restrict__ p, const float* __restrict__ att_h,
    const float* __restrict__ w_alpha, float* __restrict__ scores)
{
    const int b     = blockIdx.x;
    const int chunk = blockIdx.y;
    const int t     = threadIdx.x;

    __shared__ float4 ah4[ATTH_ / 4];
    __shared__ float4 wa4[ATTH_ / 4];
    for (int i = t; i < ATTH_ / 4; i += 256) {
        ah4[i] = ((const float4*)(att_h + (size_t)b * ATTH_))[i];
        wa4[i] = ((const float4*)w_alpha)[i];
    }
    __syncthreads();

    const int warp = t >> 5, lane = t & 31;
    const int s_lo = chunk * 49;
    const int s_hi = s_lo + 49;   // 196 = 4*49

    for (int s = s_lo + warp; s < s_hi; s += 8) {
        const float4* ps = (const float4*)(p + ((size_t)b * S_ + s) * ATTH_);
        // batch the 4 streaming loads up-front (independent)
        float4 v0 = __ldcs(&ps[lane]);
        float4 v1 = __ldcs(&ps[lane + 32]);
        float4 v2 = __ldcs(&ps[lane + 64]);
        float4 v3 = __ldcs(&ps[lane + 96]);

        float accA = 0.f, accB = 0.f;
        {
            float4 a = ah4[lane],      wv = wa4[lane];
            accA += fast_tanh(v0.x + a.x) * wv.x;
            accB += fast_tanh(v0.y + a.y) * wv.y;
            accA += fast_tanh(v0.z + a.z) * wv.z;
            accB += fast_tanh(v0.w + a.w) * wv.w;
        }
        {
            float4 a = ah4[lane + 32], wv = wa4[lane + 32];
            accA += fast_tanh(v1.x + a.x) * wv.x;
            accB += fast_tanh(v1.y + a.y) * wv.y;
            accA += fast_tanh(v1.z + a.z) * wv.z;
            accB += fast_tanh(v1.w + a.w) * wv.w;
        }
        {
            float4 a = ah4[lane + 64], wv = wa4[lane + 64];
            accA += fast_tanh(v2.x + a.x) * wv.x;
            accB += fast_tanh(v2.y + a.y) * wv.y;
            accA += fast_tanh(v2.z + a.z) * wv.z;
            accB += fast_tanh(v2.w + a.w) * wv.w;
        }
        {
            float4 a = ah4[lane + 96], wv = wa4[lane + 96];
            accA += fast_tanh(v3.x + a.x) * wv.x;
            accB += fast_tanh(v3.y + a.y) * wv.y;
            accA += fast_tanh(v3.z + a.z) * wv.z;
            accB += fast_tanh(v3.w + a.w) * wv.w;
        }
        float acc = accA + accB;
        #pragma unroll
        for (int o = 16; o; o >>= 1)
            acc += __shfl_xor_sync(0xffffffffu, acc, o);
        if (lane == 0) scores[(size_t)b * S_ + s] = acc;
    }
}

// ---------------------------------------------------------------------------
// K3a: partial weighted sums with fused (recomputed) softmax.
// part[split][b][d] = sum_{s in chunk} softmax(scores[b,:])[s] * att[b,s,d]
// grid = (B, NSPLIT) = 1792 blocks, 128 threads; thread owns TWO float4 cols
// (d = t and d = t+128 in float4 units) -> 2 independent load streams.
// Softmax over the 196 scores is recomputed identically (deterministically)
// in every block -- removes the k2b kernel + its serialization.
// ---------------------------------------------------------------------------
__global__ __launch_bounds__(128) void k3a_partial(
    const float* __restrict__ att, const float* __restrict__ scores,
    float* __restrict__ part)
{
    const int b     = blockIdx.x;
    const int split = blockIdx.y;
    const int t     = threadIdx.x;
    const int s_lo  = split * SCHUNK;

    __shared__ float es[S_];
    __shared__ float red[128];
    __shared__ float w_s[SCHUNK];

    // --- inline softmax over scores[b, 0..195] ---
    float v0 = (t < S_)       ? scores[(size_t)b * S_ + t]       : -INFINITY;
    float v1 = (t + 128 < S_) ? scores[(size_t)b * S_ + t + 128] : -INFINITY;
    red[t] = fmaxf(v0, v1);
    __syncthreads();
    #pragma unroll
    for (int o = 64; o; o >>= 1) {
        if (t < o) red[t] = fmaxf(red[t], red[t + o]);
        __syncthreads();
    }
    const float m = red[0];
    __syncthreads();
    float e0 = (t < S_)       ? __expf(v0 - m) : 0.f;
    float e1 = (t + 128 < S_) ? __expf(v1 - m) : 0.f;
    if (t < S_)       es[t]       = e0;
    if (t + 128 < S_) es[t + 128] = e1;
    red[t] = e0 + e1;
    __syncthreads();
    #pragma unroll
    for (int o = 64; o; o >>= 1) {
        if (t < o) red[t] += red[t + o];
        __syncthreads();
    }
    const float inv = 1.f / red[0];
    __syncthreads();
    if (t < SCHUNK) w_s[t] = es[s_lo + t] * inv;
    __syncthreads();

    // --- weighted partial sum, 2 float4 columns per thread ---
    const float4* ap = (const float4*)(att + ((size_t)b * S_ + s_lo) * RNN_);
    float4 acc0 = make_float4(0.f, 0.f, 0.f, 0.f);
    float4 acc1 = make_float4(0.f, 0.f, 0.f, 0.f);
    #pragma unroll 7
    for (int s = 0; s < SCHUNK; s++) {
        const float w = w_s[s];
        const float4 va = __ldcs(&ap[(size_t)s * (RNN_ / 4) + t]);
        const float4 vb = __ldcs(&ap[(size_t)s * (RNN_ / 4) + t + 128]);
        acc0.x += w * va.x; acc0.y += w * va.y;
        acc0.z += w * va.z; acc0.w += w * va.w;
        acc1.x += w * vb.x; acc1.y += w * vb.y;
        acc1.z += w * vb.z; acc1.w += w * vb.w;
    }
    float4* op = (float4*)(part + ((size_t)split * B_ + b) * RNN_);
    op[t]       = acc0;
    op[t + 128] = acc1;
}

// ---------------------------------------------------------------------------
// K3b: out[b,d] = sum_split part[split][b][d]   (deterministic reduce)
// grid = 256 blocks x 256 threads; thread owns one float4 of out.
// ---------------------------------------------------------------------------
__global__ __launch_bounds__(256) void k3b_reduce(
    const float* __restrict__ part, float* __restrict__ out)
{
    const int idx = blockIdx.x * 256 + threadIdx.x;   // 0 .. B*RNN/4-1
    const float4* p4 = (const float4*)part;
    const int stride = B_ * RNN_ / 4;                 // 65536

    float4 a0 = p4[idx];
    float4 a1 = p4[idx + stride];
    float4 a2 = p4[idx + 2 * stride];
    float4 a3 = p4[idx + 3 * stride];
    float4 a4 = p4[idx + 4 * stride];
    float4 a5 = p4[idx + 5 * stride];
    float4 a6 = p4[idx + 6 * stride];
    float4 r;
    r.x = ((a0.x + a1.x) + (a2.x + a3.x)) + ((a4.x + a5.x) + a6.x);
    r.y = ((a0.y + a1.y) + (a2.y + a3.y)) + ((a4.y + a5.y) + a6.y);
    r.z = ((a0.z + a1.z) + (a2.z + a3.z)) + ((a4.z + a5.z) + a6.z);
    r.w = ((a0.w + a1.w) + (a2.w + a3.w)) + ((a4.w + a5.w) + a6.w);
    ((float4*)out)[idx] = r;
}

// ---------------------------------------------------------------------------
extern "C" void kernel_launch(void* const* d_in, const int* in_sizes, int n_in,
                              void* d_out, int out_size)
{
    const float* h        = (const float*)d_in[0];  // [B, RNN]
    const float* att      = (const float*)d_in[1];  // [B, S, RNN]
    const float* p        = (const float*)d_in[2];  // [B, S, ATTH]
    const float* w_h2att  = (const float*)d_in[3];  // [ATTH, RNN]
    const float* b_h2att  = (const float*)d_in[4];  // [ATTH]
    const float* w_alpha  = (const float*)d_in[5];  // [1, ATTH]
    // d_in[6] = b_alpha: softmax-invariant, unused
    float* out = (float*)d_out;                     // [B, RNN]

    float *att_h_ptr = nullptr, *sc_ptr = nullptr, *part_ptr = nullptr;
    cudaGetSymbolAddress((void**)&att_h_ptr, g_att_h);
    cudaGetSymbolAddress((void**)&sc_ptr,    g_scores);
    cudaGetSymbolAddress((void**)&part_ptr,  g_part);

    k1_h2att<<<dim3(ATTH_ / 32, B_ / 32), 256>>>(h, w_h2att, b_h2att, att_h_ptr);
    k2a_scores<<<dim3(B_, 4), 256>>>(p, att_h_ptr, w_alpha, sc_ptr);
    k3a_partial<<<dim3(B_, NSPLIT), 128>>>(att, sc_ptr, part_ptr);
    k3b_reduce<<<B_ * RNN_ / 4 / 256, 256>>>(part_ptr, out);
}

// round 5
// speedup vs baseline: 1.6094x; 1.1396x over previous
#include <cuda_runtime.h>
#include <math.h>

// Problem constants (fixed by the dataset)
#define B_    256
#define S_    196
#define RNN_  1024
#define ATTH_ 512
#define NSPLIT 7
#define SCHUNK 28   // 196 / 7
#define KSPLIT 2

// Scratch (allocation-free: __device__ globals)
__device__ float g_att_h_part[KSPLIT * B_ * ATTH_];  // 1 MB  (k1 partials)
__device__ float g_scores[B_ * S_];                  // 200 KB
__device__ float g_part[NSPLIT * B_ * RNN_];         // 7 MB  (k3 partials)

// ---------------------------------------------------------------------------
// fast tanh: tanh(x) = 1 - 2/(exp(2x)+1). 2 MUFU + ~4 FMA, abs err ~1e-7.
// ---------------------------------------------------------------------------
__device__ __forceinline__ float fast_tanh(float x)
{
    float e = __expf(2.0f * x);
    return 1.0f - __fdividef(2.0f, e + 1.0f);
}

// ---------------------------------------------------------------------------
// K1: partial att_h: part[kz][b][a] = sum_{k in half kz} h[b,k] * W[a,k]
// 32x32 tiles, BK=32, split-k=2, double-buffered smem.
// grid = (16, 8, 2) = 256 blocks, 256 threads, 2x2 microtile.
// ---------------------------------------------------------------------------
__global__ __launch_bounds__(256) void k1_h2att(
    const float* __restrict__ h, const float* __restrict__ w,
    float* __restrict__ part)
{
    __shared__ float sh[2][32][34];
    __shared__ float sw[2][32][34];

    const int t  = threadIdx.x;
    const int a0 = blockIdx.x * 32;
    const int b0 = blockIdx.y * 32;
    const int kz = blockIdx.z;
    const int tx = t & 15;
    const int ty = t >> 4;
    const int lr = t >> 3;
    const int lc = (t & 7) * 4;

    const float* hrow = &h[(size_t)(b0 + lr) * RNN_ + (size_t)kz * (RNN_ / KSPLIT) + lc];
    const float* wrow = &w[(size_t)(a0 + lr) * RNN_ + (size_t)kz * (RNN_ / KSPLIT) + lc];

    // preload tile 0
    float4 hv = *(const float4*)hrow;
    float4 wv = *(const float4*)wrow;
    sh[0][lc + 0][lr] = hv.x; sh[0][lc + 1][lr] = hv.y;
    sh[0][lc + 2][lr] = hv.z; sh[0][lc + 3][lr] = hv.w;
    sw[0][lc + 0][lr] = wv.x; sw[0][lc + 1][lr] = wv.y;
    sw[0][lc + 2][lr] = wv.z; sw[0][lc + 3][lr] = wv.w;
    __syncthreads();

    float acc00 = 0.f, acc01 = 0.f, acc10 = 0.f, acc11 = 0.f;

    const int NT = RNN_ / KSPLIT / 32;   // 16 k-tiles
    #pragma unroll
    for (int kt = 0; kt < NT; kt++) {
        const int buf = kt & 1;
        if (kt + 1 < NT) {                       // prefetch next tile
            hv = *(const float4*)(hrow + (kt + 1) * 32);
            wv = *(const float4*)(wrow + (kt + 1) * 32);
        }
        #pragma unroll
        for (int kk = 0; kk < 32; kk++) {
            float2 hb = *(const float2*)&sh[buf][kk][ty * 2];
            float2 wb = *(const float2*)&sw[buf][kk][tx * 2];
            acc00 += hb.x * wb.x;
            acc01 += hb.x * wb.y;
            acc10 += hb.y * wb.x;
            acc11 += hb.y * wb.y;
        }
        __syncthreads();
        if (kt + 1 < NT) {
            const int nb = buf ^ 1;
            sh[nb][lc + 0][lr] = hv.x; sh[nb][lc + 1][lr] = hv.y;
            sh[nb][lc + 2][lr] = hv.z; sh[nb][lc + 3][lr] = hv.w;
            sw[nb][lc + 0][lr] = wv.x; sw[nb][lc + 1][lr] = wv.y;
            sw[nb][lc + 2][lr] = wv.z; sw[nb][lc + 3][lr] = wv.w;
            __syncthreads();
        }
    }

    const int bb = b0 + ty * 2;
    const int aa = a0 + tx * 2;
    float* op = part + (size_t)kz * B_ * ATTH_;
    op[(size_t)bb * ATTH_ + aa]           = acc00;
    op[(size_t)bb * ATTH_ + aa + 1]       = acc01;
    op[(size_t)(bb + 1) * ATTH_ + aa]     = acc10;
    op[(size_t)(bb + 1) * ATTH_ + aa + 1] = acc11;
}

// ---------------------------------------------------------------------------
// K2a: scores[b,s] = sum_a tanh(p[b,s,a] + att_h[b,a]) * w_alpha[a]
// att_h assembled in smem from the two k1 partials + bias.
// grid = (B, 4), 256 threads. Each warp processes TWO s-rows at a time
// (8 independent float4 streaming loads in flight).
// ---------------------------------------------------------------------------
__global__ __launch_bounds__(256) void k2a_scores(
    const float* __restrict__ p, const float* __restrict__ att_h_part,
    const float* __restrict__ bias, const float* __restrict__ w_alpha,
    float* __restrict__ scores)
{
    const int b     = blockIdx.x;
    const int chunk = blockIdx.y;
    const int t     = threadIdx.x;

    __shared__ float4 ah4[ATTH_ / 4];
    __shared__ float4 wa4[ATTH_ / 4];
    {
        const float4* p0 = (const float4*)(att_h_part + (size_t)b * ATTH_);
        const float4* p1 = (const float4*)(att_h_part + (size_t)(B_ + b) * ATTH_);
        const float4* bz = (const float4*)bias;
        for (int i = t; i < ATTH_ / 4; i += 256) {
            float4 x = p0[i], y = p1[i], z = bz[i];
            ah4[i] = make_float4(x.x + y.x + z.x, x.y + y.y + z.y,
                                 x.z + y.z + z.z, x.w + y.w + z.w);
            wa4[i] = ((const float4*)w_alpha)[i];
        }
    }
    __syncthreads();

    const int warp = t >> 5, lane = t & 31;
    const int s_lo = chunk * 49;

    // 24 row-pairs (rows 0..47 of the chunk), 3 pairs per warp
    for (int pair = warp; pair < 24; pair += 8) {
        const int s = s_lo + pair * 2;
        const float4* ps0 = (const float4*)(p + ((size_t)b * S_ + s) * ATTH_);
        const float4* ps1 = ps0 + ATTH_ / 4;

        float4 u0 = __ldcs(&ps0[lane]);
        float4 u1 = __ldcs(&ps0[lane + 32]);
        float4 u2 = __ldcs(&ps0[lane + 64]);
        float4 u3 = __ldcs(&ps0[lane + 96]);
        float4 q0 = __ldcs(&ps1[lane]);
        float4 q1 = __ldcs(&ps1[lane + 32]);
        float4 q2 = __ldcs(&ps1[lane + 64]);
        float4 q3 = __ldcs(&ps1[lane + 96]);

        float accA = 0.f, accB = 0.f;
        {
            float4 a = ah4[lane],      wv = wa4[lane];
            accA += fast_tanh(u0.x + a.x) * wv.x + fast_tanh(u0.y + a.y) * wv.y
                  + fast_tanh(u0.z + a.z) * wv.z + fast_tanh(u0.w + a.w) * wv.w;
            accB += fast_tanh(q0.x + a.x) * wv.x + fast_tanh(q0.y + a.y) * wv.y
                  + fast_tanh(q0.z + a.z) * wv.z + fast_tanh(q0.w + a.w) * wv.w;
        }
        {
            float4 a = ah4[lane + 32], wv = wa4[lane + 32];
            accA += fast_tanh(u1.x + a.x) * wv.x + fast_tanh(u1.y + a.y) * wv.y
                  + fast_tanh(u1.z + a.z) * wv.z + fast_tanh(u1.w + a.w) * wv.w;
            accB += fast_tanh(q1.x + a.x) * wv.x + fast_tanh(q1.y + a.y) * wv.y
                  + fast_tanh(q1.z + a.z) * wv.z + fast_tanh(q1.w + a.w) * wv.w;
        }
        {
            float4 a = ah4[lane + 64], wv = wa4[lane + 64];
            accA += fast_tanh(u2.x + a.x) * wv.x + fast_tanh(u2.y + a.y) * wv.y
                  + fast_tanh(u2.z + a.z) * wv.z + fast_tanh(u2.w + a.w) * wv.w;
            accB += fast_tanh(q2.x + a.x) * wv.x + fast_tanh(q2.y + a.y) * wv.y
                  + fast_tanh(q2.z + a.z) * wv.z + fast_tanh(q2.w + a.w) * wv.w;
        }
        {
            float4 a = ah4[lane + 96], wv = wa4[lane + 96];
            accA += fast_tanh(u3.x + a.x) * wv.x + fast_tanh(u3.y + a.y) * wv.y
                  + fast_tanh(u3.z + a.z) * wv.z + fast_tanh(u3.w + a.w) * wv.w;
            accB += fast_tanh(q3.x + a.x) * wv.x + fast_tanh(q3.y + a.y) * wv.y
                  + fast_tanh(q3.z + a.z) * wv.z + fast_tanh(q3.w + a.w) * wv.w;
        }
        #pragma unroll
        for (int o = 16; o; o >>= 1) {
            accA += __shfl_xor_sync(0xffffffffu, accA, o);
            accB += __shfl_xor_sync(0xffffffffu, accB, o);
        }
        if (lane == 0) {
            scores[(size_t)b * S_ + s]     = accA;
            scores[(size_t)b * S_ + s + 1] = accB;
        }
    }

    // tail row (chunk-local row 48) handled by warp 0
    if (warp == 0) {
        const int s = s_lo + 48;
        const float4* ps = (const float4*)(p + ((size_t)b * S_ + s) * ATTH_);
        float4 v0 = __ldcs(&ps[lane]);
        float4 v1 = __ldcs(&ps[lane + 32]);
        float4 v2 = __ldcs(&ps[lane + 64]);
        float4 v3 = __ldcs(&ps[lane + 96]);
        float acc = 0.f;
        {
            float4 a = ah4[lane],      wv = wa4[lane];
            acc += fast_tanh(v0.x + a.x) * wv.x + fast_tanh(v0.y + a.y) * wv.y
                 + fast_tanh(v0.z + a.z) * wv.z + fast_tanh(v0.w + a.w) * wv.w;
        }
        {
            float4 a = ah4[lane + 32], wv = wa4[lane + 32];
            acc += fast_tanh(v1.x + a.x) * wv.x + fast_tanh(v1.y + a.y) * wv.y
                 + fast_tanh(v1.z + a.z) * wv.z + fast_tanh(v1.w + a.w) * wv.w;
        }
        {
            float4 a = ah4[lane + 64], wv = wa4[lane + 64];
            acc += fast_tanh(v2.x + a.x) * wv.x + fast_tanh(v2.y + a.y) * wv.y
                 + fast_tanh(v2.z + a.z) * wv.z + fast_tanh(v2.w + a.w) * wv.w;
        }
        {
            float4 a = ah4[lane + 96], wv = wa4[lane + 96];
            acc += fast_tanh(v3.x + a.x) * wv.x + fast_tanh(v3.y + a.y) * wv.y
                 + fast_tanh(v3.z + a.z) * wv.z + fast_tanh(v3.w + a.w) * wv.w;
        }
        #pragma unroll
        for (int o = 16; o; o >>= 1)
            acc += __shfl_xor_sync(0xffffffffu, acc, o);
        if (lane == 0) scores[(size_t)b * S_ + s] = acc;
    }
}

// ---------------------------------------------------------------------------
// K3a: partial weighted sums with fused (recomputed, deterministic) softmax.
// grid = (B, NSPLIT) = 1792 blocks, 128 threads; thread owns TWO float4 cols.
// ---------------------------------------------------------------------------
__global__ __launch_bounds__(128) void k3a_partial(
    const float* __restrict__ att, const float* __restrict__ scores,
    float* __restrict__ part)
{
    const int b     = blockIdx.x;
    const int split = blockIdx.y;
    const int t     = threadIdx.x;
    const int s_lo  = split * SCHUNK;

    __shared__ float es[S_];
    __shared__ float red[128];
    __shared__ float w_s[SCHUNK];

    // --- inline softmax over scores[b, 0..195] ---
    float v0 = (t < S_)       ? scores[(size_t)b * S_ + t]       : -INFINITY;
    float v1 = (t + 128 < S_) ? scores[(size_t)b * S_ + t + 128] : -INFINITY;
    red[t] = fmaxf(v0, v1);
    __syncthreads();
    #pragma unroll
    for (int o = 64; o; o >>= 1) {
        if (t < o) red[t] = fmaxf(red[t], red[t + o]);
        __syncthreads();
    }
    const float m = red[0];
    __syncthreads();
    float e0 = (t < S_)       ? __expf(v0 - m) : 0.f;
    float e1 = (t + 128 < S_) ? __expf(v1 - m) : 0.f;
    if (t < S_)       es[t]       = e0;
    if (t + 128 < S_) es[t + 128] = e1;
    red[t] = e0 + e1;
    __syncthreads();
    #pragma unroll
    for (int o = 64; o; o >>= 1) {
        if (t < o) red[t] += red[t + o];
        __syncthreads();
    }
    const float inv = 1.f / red[0];
    __syncthreads();
    if (t < SCHUNK) w_s[t] = es[s_lo + t] * inv;
    __syncthreads();

    // --- weighted partial sum, 2 float4 columns per thread ---
    const float4* ap = (const float4*)(att + ((size_t)b * S_ + s_lo) * RNN_);
    float4 acc0 = make_float4(0.f, 0.f, 0.f, 0.f);
    float4 acc1 = make_float4(0.f, 0.f, 0.f, 0.f);
    #pragma unroll 7
    for (int s = 0; s < SCHUNK; s++) {
        const float w = w_s[s];
        const float4 va = __ldcs(&ap[(size_t)s * (RNN_ / 4) + t]);
        const float4 vb = __ldcs(&ap[(size_t)s * (RNN_ / 4) + t + 128]);
        acc0.x += w * va.x; acc0.y += w * va.y;
        acc0.z += w * va.z; acc0.w += w * va.w;
        acc1.x += w * vb.x; acc1.y += w * vb.y;
        acc1.z += w * vb.z; acc1.w += w * vb.w;
    }
    float4* op = (float4*)(part + ((size_t)split * B_ + b) * RNN_);
    op[t]       = acc0;
    op[t + 128] = acc1;
}

// ---------------------------------------------------------------------------
// K3b: out[b,d] = sum_split part[split][b][d]   (deterministic reduce)
// float2 granularity: 131072 threads for latency hiding.
// ---------------------------------------------------------------------------
__global__ __launch_bounds__(256) void k3b_reduce(
    const float* __restrict__ part, float* __restrict__ out)
{
    const int idx = blockIdx.x * 256 + threadIdx.x;   // 0 .. B*RNN/2-1
    const float2* p2 = (const float2*)part;
    const int stride = B_ * RNN_ / 2;                 // 131072

    float2 a0 = p2[idx];
    float2 a1 = p2[idx + stride];
    float2 a2 = p2[idx + 2 * stride];
    float2 a3 = p2[idx + 3 * stride];
    float2 a4 = p2[idx + 4 * stride];
    float2 a5 = p2[idx + 5 * stride];
    float2 a6 = p2[idx + 6 * stride];
    float2 r;
    r.x = ((a0.x + a1.x) + (a2.x + a3.x)) + ((a4.x + a5.x) + a6.x);
    r.y = ((a0.y + a1.y) + (a2.y + a3.y)) + ((a4.y + a5.y) + a6.y);
    ((float2*)out)[idx] = r;
}

// ---------------------------------------------------------------------------
extern "C" void kernel_launch(void* const* d_in, const int* in_sizes, int n_in,
                              void* d_out, int out_size)
{
    const float* h        = (const float*)d_in[0];  // [B, RNN]
    const float* att      = (const float*)d_in[1];  // [B, S, RNN]
    const float* p        = (const float*)d_in[2];  // [B, S, ATTH]
    const float* w_h2att  = (const float*)d_in[3];  // [ATTH, RNN]
    const float* b_h2att  = (const float*)d_in[4];  // [ATTH]
    const float* w_alpha  = (const float*)d_in[5];  // [1, ATTH]
    // d_in[6] = b_alpha: softmax-invariant, unused
    float* out = (float*)d_out;                     // [B, RNN]

    float *ahp_ptr = nullptr, *sc_ptr = nullptr, *part_ptr = nullptr;
    cudaGetSymbolAddress((void**)&ahp_ptr,  g_att_h_part);
    cudaGetSymbolAddress((void**)&sc_ptr,   g_scores);
    cudaGetSymbolAddress((void**)&part_ptr, g_part);

    k1_h2att<<<dim3(ATTH_ / 32, B_ / 32, KSPLIT), 256>>>(h, w_h2att, ahp_ptr);
    k2a_scores<<<dim3(B_, 4), 256>>>(p, ahp_ptr, b_h2att, w_alpha, sc_ptr);
    k3a_partial<<<dim3(B_, NSPLIT), 128>>>(att, sc_ptr, part_ptr);
    k3b_reduce<<<B_ * RNN_ / 2 / 256, 256>>>(part_ptr, out);
}